// round 15
// baseline (speedup 1.0000x reference)
#include <cuda_runtime.h>

// ----------------------------------------------------------------------------
// Tropical (max-plus) ViT, fp32.  C[m,n] = max_k (A[m,k]+B[n,k]) everywhere.
// Round 14: r9 structure + duplicated-A smem ((a,a) f32x2 pairs) so the
// FADD2 inner loop needs no per-k dup MOVs: 16 -> 14 slots per k-step.
// (max.f32x2 does not exist on sm_103a; accumulate stays scalar FMNMX.)
// ----------------------------------------------------------------------------

#define NEG_INF (-3.0e38f)
#define BB     8
#define NPATCH 196
#define DD     128
#define DFF    256
#define NPAD   224
#define MTOT   1568
#define NCLS   1000

__device__ float g_h  [MTOT * DD];
__device__ float g_rmH[MTOT];
__device__ float g_q  [MTOT * DD];
__device__ float g_k  [MTOT * DD];
__device__ float g_vT [BB * DD * NPAD];      // [b][d][j], j-pads stay 0
__device__ float g_s  [BB * NPATCH * NPAD];  // [b][i][j], j-pads = -inf
__device__ float g_p  [2][MTOT * DD];        // split-K parts
__device__ float g_h1 [MTOT * DFF];
// atomics: [0..5*MTOT) rowmax (embed, att0, ff0, att1, ff1), then pool
__device__ unsigned g_atoms[5 * MTOT + BB * DD];

enum { M_EMBED, M_QKV, M_SCORES, M_ATT, M_FF1, M_FF2 };

__device__ __forceinline__ unsigned f2ord(float f) {
    unsigned u = __float_as_uint(f);
    return u ^ ((unsigned)((int)u >> 31) | 0x80000000u);
}
__device__ __forceinline__ float ord2f(unsigned u) {
    unsigned v = (u & 0x80000000u) ? (u ^ 0x80000000u) : ~u;
    return __uint_as_float(v);
}

// ---------------------------------------------------------------------------
// Tropical NT GEMM: 32x32 block tile, 128 threads, 2x4 per thread.
// A tile stored duplicated ((a,a) pairs) -> FADD2 with no dup MOVs;
// scalar FMNMX accumulate.
// ---------------------------------------------------------------------------
template<int MODE>
__global__ __launch_bounds__(128) void tg(
    const float* __restrict__ A, const float* __restrict__ B,
    const float* __restrict__ B2, const float* __restrict__ B3,
    float* __restrict__ C0, float* __restrict__ C1, float* __restrict__ C2,
    const float* __restrict__ rmSub, unsigned* __restrict__ rmAtom,
    const float* __restrict__ aux,
    int M, int N, int K, int ldc,
    int aBatch, int bBatch, int cBatch,
    int splitShift, int kPerSplit)
{
    __shared__ __align__(16) float As2[32][68];  // [k][2*m] duplicated pairs
    __shared__ __align__(16) float Bs [32][36];  // [k][n]

    const int t  = threadIdx.x;
    const int tx = t & 7;          // n group (4 cols)
    const int ty = t >> 3;         // m group (2 rows)
    const int lk = tx << 2;
    const int lr = ty;
    const int bm = blockIdx.y << 5;
    const int bn = blockIdx.x << 5;

    const int z      = blockIdx.z;
    const int half   = z & ((1 << splitShift) - 1);
    const int batch  = z >> splitShift;
    const int kBegin = half * kPerSplit;
    const int kEnd   = min(K, kBegin + kPerSplit);

    const float* Ab = A + (long)batch * aBatch;
    const float* Bb = B + (long)batch * bBatch;

    const float* arow[2];
#pragma unroll
    for (int h = 0; h < 2; ++h) {
        int ra = bm + lr + 16 * h; if (ra > M - 1) ra = M - 1;
        if (MODE == M_EMBED) {
            int b = ra / NPATCH, np = ra % NPATCH;
            arow[h] = A + ((long)(b * 224 + (np / 14) * 16)) * 224 + (np % 14) * 16;
        } else {
            arow[h] = Ab + (long)ra * K;
        }
    }
    const float* brow[2];
#pragma unroll
    for (int h = 0; h < 2; ++h) {
        int rb = bn + lr + 16 * h; if (rb > N - 1) rb = N - 1;
        if (MODE == M_QKV) {
            const float* Bp = rb < 128 ? B : (rb < 256 ? B2 : B3);
            brow[h] = Bp + (long)(rb & 127) * K;
        } else {
            brow[h] = Bb + (long)rb * K;
        }
    }

    float acc[2][4];
#pragma unroll
    for (int i = 0; i < 2; ++i)
#pragma unroll
        for (int j = 0; j < 4; ++j) acc[i][j] = NEG_INF;

    for (int kk = kBegin; kk < kEnd; kk += 32) {
#pragma unroll
        for (int h = 0; h < 2; ++h) {
            float4 va;
            if (MODE == M_EMBED) {
                int j = kk + lk; int pr = j >> 4, pc = j & 15;
                va = *(const float4*)(arow[h] + pr * 224 + pc);
            } else {
                va = *(const float4*)(arow[h] + kk + lk);
            }
            int m2 = 2 * (lr + 16 * h);
            *(float2*)&As2[lk + 0][m2] = make_float2(va.x, va.x);
            *(float2*)&As2[lk + 1][m2] = make_float2(va.y, va.y);
            *(float2*)&As2[lk + 2][m2] = make_float2(va.z, va.z);
            *(float2*)&As2[lk + 3][m2] = make_float2(va.w, va.w);

            float4 vb = *(const float4*)(brow[h] + kk + lk);
            Bs[lk + 0][lr + 16 * h] = vb.x;
            Bs[lk + 1][lr + 16 * h] = vb.y;
            Bs[lk + 2][lr + 16 * h] = vb.z;
            Bs[lk + 3][lr + 16 * h] = vb.w;
        }
        __syncthreads();
#pragma unroll
        for (int k = 0; k < 32; ++k) {
            ulonglong2 aq = *(const ulonglong2*)&As2[k][ty * 4];   // (a0,a0),(a1,a1)
            ulonglong2 bq = *(const ulonglong2*)&Bs[k][tx * 4];    // (b0,b1),(b2,b3)
            unsigned long long t0, t1, t2, t3;
            asm("add.rn.f32x2 %0, %1, %2;" : "=l"(t0) : "l"(aq.x), "l"(bq.x));
            asm("add.rn.f32x2 %0, %1, %2;" : "=l"(t1) : "l"(aq.x), "l"(bq.y));
            asm("add.rn.f32x2 %0, %1, %2;" : "=l"(t2) : "l"(aq.y), "l"(bq.x));
            asm("add.rn.f32x2 %0, %1, %2;" : "=l"(t3) : "l"(aq.y), "l"(bq.y));
            float e0, e1;
            asm("mov.b64 {%0, %1}, %2;" : "=f"(e0), "=f"(e1) : "l"(t0));
            acc[0][0] = fmaxf(acc[0][0], e0);
            acc[0][1] = fmaxf(acc[0][1], e1);
            asm("mov.b64 {%0, %1}, %2;" : "=f"(e0), "=f"(e1) : "l"(t1));
            acc[0][2] = fmaxf(acc[0][2], e0);
            acc[0][3] = fmaxf(acc[0][3], e1);
            asm("mov.b64 {%0, %1}, %2;" : "=f"(e0), "=f"(e1) : "l"(t2));
            acc[1][0] = fmaxf(acc[1][0], e0);
            acc[1][1] = fmaxf(acc[1][1], e1);
            asm("mov.b64 {%0, %1}, %2;" : "=f"(e0), "=f"(e1) : "l"(t3));
            acc[1][2] = fmaxf(acc[1][2], e0);
            acc[1][3] = fmaxf(acc[1][3], e1);
        }
        __syncthreads();
    }

    // ---- epilogue ----
    const bool atomicMode = (MODE == M_EMBED || MODE == M_ATT || MODE == M_FF2);
    float rsub[2] = { 0.f, 0.f };
    if (MODE == M_QKV || MODE == M_FF1) {
        int r0 = bm + ty * 2;
        rsub[0] = rmSub[min(r0, M - 1)];
        rsub[1] = rmSub[min(r0 + 1, M - 1)];
    }
    const float tauv = (MODE == M_FF1) ? aux[0] : 0.f;
    float* Ch = (half ? C1 : C0) + (long)batch * cBatch;

    float rmax2[2] = { NEG_INF, NEG_INF };
#pragma unroll
    for (int i = 0; i < 2; ++i) {
        int m = bm + ty * 2 + i;
        bool ok = (m < M);
#pragma unroll
        for (int j = 0; j < 4; ++j) {
            int n = bn + tx * 4 + j;
            float v = acc[i][j];
            if (MODE == M_EMBED) v += aux[(m % NPATCH) * DD + n];
            if (MODE == M_QKV || MODE == M_FF1) v -= rsub[i];
            if (MODE == M_FF1) v = fmaxf(v, tauv);
            if (atomicMode) rmax2[i] = fmaxf(rmax2[i], v);
            if (!ok) continue;
            if (MODE == M_QKV) {
                if (n < DD)            C0[(long)m * DD + n] = v;
                else if (n < 2 * DD)   C1[(long)m * DD + (n - DD)] = v;
                else {
                    int b = m / NPATCH, ii = m % NPATCH;
                    C2[((long)b * DD + (n - 2 * DD)) * NPAD + ii] = v;
                }
            } else if (MODE == M_SCORES) {
                Ch[(long)m * ldc + n] = (n < N) ? v : NEG_INF;
            } else {
                Ch[(long)m * ldc + n] = v;
            }
        }
    }

    if (atomicMode) {
#pragma unroll
        for (int i = 0; i < 2; ++i) {
            float rm = rmax2[i];
#pragma unroll
            for (int o = 1; o < 8; o <<= 1)
                rm = fmaxf(rm, __shfl_xor_sync(0xffffffffu, rm, o));
            int m = bm + ty * 2 + i;
            if (tx == 0 && m < M) {
                int row = (MODE == M_ATT) ? batch * NPATCH + m : m;
                atomicMax(&rmAtom[row], f2ord(rm));
            }
        }
    }
}

// h = max(p0,p1); rmH = decode(atomic)     (single pass, no barrier)
__global__ void combine2_k(const float* __restrict__ p0, const float* __restrict__ p1,
                           const unsigned* __restrict__ rmSrc,
                           float* __restrict__ h, float* __restrict__ rmH)
{
    int r = blockIdx.x, t = threadIdx.x;
    long idx = (long)r * DD + t;
    h[idx] = fmaxf(p0[idx], p1[idx]);
    if (t == 0) rmH[r] = ord2f(rmSrc[r]);
}

// h = max(h, max(p0,p1) - rmA[r]); rmH = max(rmH,0); optional pool atomic
__global__ void resid2_k(const float* __restrict__ p0, const float* __restrict__ p1,
                         const unsigned* __restrict__ rmA,
                         float* __restrict__ h, float* __restrict__ rmH,
                         unsigned* __restrict__ poolAtom)
{
    int r = blockIdx.x, t = threadIdx.x;
    long idx = (long)r * DD + t;
    float av = fmaxf(p0[idx], p1[idx]);
    float hv = fmaxf(h[idx], av - ord2f(rmA[r]));
    h[idx] = hv;
    if (t == 0) rmH[r] = fmaxf(rmH[r], 0.f);
    if (poolAtom) atomicMax(&poolAtom[(r / NPATCH) * DD + t], f2ord(hv));
}

// logits[b,c] = max_d(pooled[b,d] + W[c,d]) * ls
__global__ void head_k(const float* __restrict__ W, const float* __restrict__ ls,
                       const unsigned* __restrict__ poolAtom, float* __restrict__ out)
{
    __shared__ float p[DD];
    int b = blockIdx.y, t = threadIdx.x;
    p[t] = ord2f(poolAtom[b * DD + t]);
    __syncthreads();
    int c = blockIdx.x * 128 + t;
    if (c < NCLS) {
        float acc = NEG_INF;
        const float* w = W + (long)c * DD;
#pragma unroll 4
        for (int d = 0; d < DD; ++d) acc = fmaxf(acc, p[d] + w[d]);
        out[(long)b * NCLS + c] = acc * ls[0];
    }
}

// ---------------------------------------------------------------------------

extern "C" void kernel_launch(void* const* d_in, const int* in_sizes, int n_in,
                              void* d_out, int out_size)
{
    (void)in_sizes; (void)n_in; (void)out_size;
    const float* x       = (const float*)d_in[0];
    const float* embed_W = (const float*)d_in[1];
    const float* pos     = (const float*)d_in[2];
    const float* head_W  = (const float*)d_in[15];
    const float* lscale  = (const float*)d_in[16];
    float* out = (float*)d_out;

    float *h, *rmH, *q, *k, *vT, *s, *p, *h1;
    unsigned* at;
    cudaGetSymbolAddress((void**)&h,   g_h);
    cudaGetSymbolAddress((void**)&rmH, g_rmH);
    cudaGetSymbolAddress((void**)&q,   g_q);
    cudaGetSymbolAddress((void**)&k,   g_k);
    cudaGetSymbolAddress((void**)&vT,  g_vT);
    cudaGetSymbolAddress((void**)&s,   g_s);
    cudaGetSymbolAddress((void**)&p,   g_p);
    cudaGetSymbolAddress((void**)&h1,  g_h1);
    cudaGetSymbolAddress((void**)&at,  g_atoms);

    float* p1 = p + MTOT * DD;
    unsigned* rmE     = at;
    unsigned* poolAt  = at + 5 * MTOT;

    cudaMemsetAsync(at, 0, (5 * MTOT + BB * DD) * sizeof(unsigned));

    // embed: patchify fused, K=256 split2 -> p0/p1 ; +pos & rowmax in epilogue
    tg<M_EMBED><<<dim3(4, 49, 2), 128>>>(x, embed_W, 0, 0, p, p1, 0,
        0, rmE, pos, MTOT, DD, 256, DD, 0, 0, 0, 1, 128);
    combine2_k<<<MTOT, 128>>>(p, p1, rmE, h, rmH);

    for (int l = 0; l < 2; ++l) {
        const float* qW  = (const float*)d_in[3 + 6 * l];
        const float* kW  = (const float*)d_in[4 + 6 * l];
        const float* vW  = (const float*)d_in[5 + 6 * l];
        const float* f1W = (const float*)d_in[6 + 6 * l];
        const float* f2W = (const float*)d_in[7 + 6 * l];
        const float* tau = (const float*)d_in[8 + 6 * l];
        unsigned* rmAt = at + (1 + 2 * l) * MTOT;
        unsigned* rmFf = at + (2 + 2 * l) * MTOT;

        // q/k/v fused (N=384): A=h, epilogue subtracts rmH
        tg<M_QKV><<<dim3(12, 49, 1), 128>>>(h, qW, kW, vW, q, k, vT,
            rmH, 0, 0, MTOT, 384, DD, 0, 0, 0, 0, 0, DD);

        // scores per batch: (196x128) x (196x128)^T -> (196 x 224), pads -inf
        tg<M_SCORES><<<dim3(7, 7, 8), 128>>>(q, k, 0, 0, s, 0, 0,
            0, 0, 0, NPATCH, NPATCH, DD, NPAD,
            NPATCH * DD, NPATCH * DD, NPATCH * NPAD, 0, DD);

        // attn out per batch: K=224 split2 -> p0/p1 + atomic rowmax
        tg<M_ATT><<<dim3(4, 7, 16), 128>>>(s, vT, 0, 0, p, p1, 0,
            0, rmAt, 0, NPATCH, DD, NPAD, DD,
            NPATCH * NPAD, DD * NPAD, NPATCH * DD, 1, 128);
        resid2_k<<<MTOT, 128>>>(p, p1, rmAt, h, rmH, 0);

        // ff1: A=h, epilogue subtracts rmH then max(tau) -> h1
        tg<M_FF1><<<dim3(8, 49, 1), 128>>>(h, f1W, 0, 0, h1, 0, 0,
            rmH, 0, tau, MTOT, DFF, DD, DFF, 0, 0, 0, 0, DD);

        // ff2: K=256 split2 -> p0/p1 + atomic rowmax
        tg<M_FF2><<<dim3(4, 49, 2), 128>>>(h1, f2W, 0, 0, p, p1, 0,
            0, rmFf, 0, MTOT, DD, DFF, DD, 0, 0, 0, 1, 128);
        resid2_k<<<MTOT, 128>>>(p, p1, rmFf, h, rmH,
                                (l == 1) ? poolAt : 0);
    }

    head_k<<<dim3(8, BB), 128>>>(head_W, lscale, poolAt, out);
}

// round 16
// speedup vs baseline: 1.1728x; 1.1728x over previous
#include <cuda_runtime.h>

// ----------------------------------------------------------------------------
// Tropical (max-plus) ViT, fp32.  C[m,n] = max_k (A[m,k]+B[n,k]) everywhere.
// Round 15: r9/r11 champion (125.4us) + coalesced vT epilogue (smem transpose)
// + float4-vectorized follower kernels (392 blocks instead of 1568).
// GEMM inner loop byte-identical to the champion.
// ----------------------------------------------------------------------------

#define NEG_INF (-3.0e38f)
#define BB     8
#define NPATCH 196
#define DD     128
#define DFF    256
#define NPAD   224
#define MTOT   1568
#define NCLS   1000

__device__ float g_h  [MTOT * DD];
__device__ float g_rmH[MTOT];
__device__ float g_q  [MTOT * DD];
__device__ float g_k  [MTOT * DD];
__device__ float g_vT [BB * DD * NPAD];      // [b][d][j], j-pads stay 0
__device__ float g_s  [BB * NPATCH * NPAD];  // [b][i][j], j-pads = -inf
__device__ float g_p  [2][MTOT * DD];        // split-K parts
__device__ float g_h1 [MTOT * DFF];
// atomics: [0..5*MTOT) rowmax (embed, att0, ff0, att1, ff1), then pool
__device__ unsigned g_atoms[5 * MTOT + BB * DD];

enum { M_EMBED, M_QKV, M_SCORES, M_ATT, M_FF1, M_FF2 };

__device__ __forceinline__ unsigned f2ord(float f) {
    unsigned u = __float_as_uint(f);
    return u ^ ((unsigned)((int)u >> 31) | 0x80000000u);
}
__device__ __forceinline__ float ord2f(unsigned u) {
    unsigned v = (u & 0x80000000u) ? (u ^ 0x80000000u) : ~u;
    return __uint_as_float(v);
}

// ---------------------------------------------------------------------------
// Tropical NT GEMM: 32x32 block tile, 128 threads, 2x4 per thread, FADD2.
// ---------------------------------------------------------------------------
template<int MODE>
__global__ __launch_bounds__(128) void tg(
    const float* __restrict__ A, const float* __restrict__ B,
    const float* __restrict__ B2, const float* __restrict__ B3,
    float* __restrict__ C0, float* __restrict__ C1, float* __restrict__ C2,
    const float* __restrict__ rmSub, unsigned* __restrict__ rmAtom,
    const float* __restrict__ aux,
    int M, int N, int K, int ldc,
    int aBatch, int bBatch, int cBatch,
    int splitShift, int kPerSplit)
{
    __shared__ __align__(16) float As[32][34];
    __shared__ __align__(16) float Bs[32][36];

    const int t  = threadIdx.x;
    const int tx = t & 7;          // n group (4 cols)
    const int ty = t >> 3;         // m group (2 rows)
    const int lk = tx << 2;
    const int lr = ty;
    const int bm = blockIdx.y << 5;
    const int bn = blockIdx.x << 5;

    const int z      = blockIdx.z;
    const int half   = z & ((1 << splitShift) - 1);
    const int batch  = z >> splitShift;
    const int kBegin = half * kPerSplit;
    const int kEnd   = min(K, kBegin + kPerSplit);

    const float* Ab = A + (long)batch * aBatch;
    const float* Bb = B + (long)batch * bBatch;

    const float* arow[2];
#pragma unroll
    for (int h = 0; h < 2; ++h) {
        int ra = bm + lr + 16 * h; if (ra > M - 1) ra = M - 1;
        if (MODE == M_EMBED) {
            int b = ra / NPATCH, np = ra % NPATCH;
            arow[h] = A + ((long)(b * 224 + (np / 14) * 16)) * 224 + (np % 14) * 16;
        } else {
            arow[h] = Ab + (long)ra * K;
        }
    }
    const float* brow[2];
#pragma unroll
    for (int h = 0; h < 2; ++h) {
        int rb = bn + lr + 16 * h; if (rb > N - 1) rb = N - 1;
        if (MODE == M_QKV) {
            const float* Bp = rb < 128 ? B : (rb < 256 ? B2 : B3);
            brow[h] = Bp + (long)(rb & 127) * K;
        } else {
            brow[h] = Bb + (long)rb * K;
        }
    }

    float acc[2][4];
#pragma unroll
    for (int i = 0; i < 2; ++i)
#pragma unroll
        for (int j = 0; j < 4; ++j) acc[i][j] = NEG_INF;

    for (int kk = kBegin; kk < kEnd; kk += 32) {
#pragma unroll
        for (int h = 0; h < 2; ++h) {
            float4 va;
            if (MODE == M_EMBED) {
                int j = kk + lk; int pr = j >> 4, pc = j & 15;
                va = *(const float4*)(arow[h] + pr * 224 + pc);
            } else {
                va = *(const float4*)(arow[h] + kk + lk);
            }
            As[lk + 0][lr + 16 * h] = va.x;
            As[lk + 1][lr + 16 * h] = va.y;
            As[lk + 2][lr + 16 * h] = va.z;
            As[lk + 3][lr + 16 * h] = va.w;

            float4 vb = *(const float4*)(brow[h] + kk + lk);
            Bs[lk + 0][lr + 16 * h] = vb.x;
            Bs[lk + 1][lr + 16 * h] = vb.y;
            Bs[lk + 2][lr + 16 * h] = vb.z;
            Bs[lk + 3][lr + 16 * h] = vb.w;
        }
        __syncthreads();
#pragma unroll
        for (int k = 0; k < 32; ++k) {
            float2 av = *(const float2*)&As[k][ty * 2];
            ulonglong2 bq = *(const ulonglong2*)&Bs[k][tx * 4];
            unsigned long long a0p, a1p, t0, t1, t2, t3;
            asm("mov.b64 %0, {%1, %1};" : "=l"(a0p) : "f"(av.x));
            asm("mov.b64 %0, {%1, %1};" : "=l"(a1p) : "f"(av.y));
            asm("add.rn.f32x2 %0, %1, %2;" : "=l"(t0) : "l"(a0p), "l"(bq.x));
            asm("add.rn.f32x2 %0, %1, %2;" : "=l"(t1) : "l"(a0p), "l"(bq.y));
            asm("add.rn.f32x2 %0, %1, %2;" : "=l"(t2) : "l"(a1p), "l"(bq.x));
            asm("add.rn.f32x2 %0, %1, %2;" : "=l"(t3) : "l"(a1p), "l"(bq.y));
            float e0, e1;
            asm("mov.b64 {%0, %1}, %2;" : "=f"(e0), "=f"(e1) : "l"(t0));
            acc[0][0] = fmaxf(acc[0][0], e0);
            acc[0][1] = fmaxf(acc[0][1], e1);
            asm("mov.b64 {%0, %1}, %2;" : "=f"(e0), "=f"(e1) : "l"(t1));
            acc[0][2] = fmaxf(acc[0][2], e0);
            acc[0][3] = fmaxf(acc[0][3], e1);
            asm("mov.b64 {%0, %1}, %2;" : "=f"(e0), "=f"(e1) : "l"(t2));
            acc[1][0] = fmaxf(acc[1][0], e0);
            acc[1][1] = fmaxf(acc[1][1], e1);
            asm("mov.b64 {%0, %1}, %2;" : "=f"(e0), "=f"(e1) : "l"(t3));
            acc[1][2] = fmaxf(acc[1][2], e0);
            acc[1][3] = fmaxf(acc[1][3], e1);
        }
        __syncthreads();
    }

    // ---- epilogue ----
    const bool atomicMode = (MODE == M_EMBED || MODE == M_ATT || MODE == M_FF2);
    float rsub[2] = { 0.f, 0.f };
    if (MODE == M_QKV || MODE == M_FF1) {
        int r0 = bm + ty * 2;
        rsub[0] = rmSub[min(r0, M - 1)];
        rsub[1] = rmSub[min(r0 + 1, M - 1)];
    }
    const float tauv = (MODE == M_FF1) ? aux[0] : 0.f;
    float* Ch = (half ? C1 : C0) + (long)batch * cBatch;

    // coalesced vT path: entire block is in the vT band
    if (MODE == M_QKV && bn >= 2 * DD) {
        // stage into As[n_local][m_local] (stride 34, conflict-free-ish)
#pragma unroll
        for (int i = 0; i < 2; ++i)
#pragma unroll
            for (int j = 0; j < 4; ++j)
                As[tx * 4 + j][ty * 2 + i] = acc[i][j] - rsub[i];
        __syncthreads();
        int lane = t & 31, wq = t >> 5;
#pragma unroll
        for (int r8 = 0; r8 < 8; ++r8) {
            int nloc = r8 * 4 + wq;
            int mg = bm + lane;
            int b = mg / NPATCH, ii = mg % NPATCH;
            C2[((long)b * DD + (bn - 2 * DD) + nloc) * NPAD + ii] = As[nloc][lane];
        }
        return;
    }

    float rmax2[2] = { NEG_INF, NEG_INF };
#pragma unroll
    for (int i = 0; i < 2; ++i) {
        int m = bm + ty * 2 + i;
        bool ok = (m < M);
#pragma unroll
        for (int j = 0; j < 4; ++j) {
            int n = bn + tx * 4 + j;
            float v = acc[i][j];
            if (MODE == M_EMBED) v += aux[(m % NPATCH) * DD + n];
            if (MODE == M_QKV || MODE == M_FF1) v -= rsub[i];
            if (MODE == M_FF1) v = fmaxf(v, tauv);
            if (atomicMode) rmax2[i] = fmaxf(rmax2[i], v);
            if (!ok) continue;
            if (MODE == M_QKV) {
                if (n < DD)            C0[(long)m * DD + n] = v;
                else                   C1[(long)m * DD + (n - DD)] = v;
            } else if (MODE == M_SCORES) {
                Ch[(long)m * ldc + n] = (n < N) ? v : NEG_INF;
            } else {
                Ch[(long)m * ldc + n] = v;
            }
        }
    }

    if (atomicMode) {
#pragma unroll
        for (int i = 0; i < 2; ++i) {
            float rm = rmax2[i];
#pragma unroll
            for (int o = 1; o < 8; o <<= 1)
                rm = fmaxf(rm, __shfl_xor_sync(0xffffffffu, rm, o));
            int m = bm + ty * 2 + i;
            if (tx == 0 && m < M) {
                int row = (MODE == M_ATT) ? batch * NPATCH + m : m;
                atomicMax(&rmAtom[row], f2ord(rm));
            }
        }
    }
}

// h = max(p0,p1); rmH = decode(atomic).  float4 per thread, 392 blocks.
__global__ void combine2_k(const float4* __restrict__ p0, const float4* __restrict__ p1,
                           const unsigned* __restrict__ rmSrc,
                           float4* __restrict__ h, float* __restrict__ rmH)
{
    int idx = blockIdx.x * 128 + threadIdx.x;     // [0, MTOT*32)
    float4 a = p0[idx], b = p1[idx];
    a.x = fmaxf(a.x, b.x); a.y = fmaxf(a.y, b.y);
    a.z = fmaxf(a.z, b.z); a.w = fmaxf(a.w, b.w);
    h[idx] = a;
    if ((idx & 31) == 0) { int r = idx >> 5; rmH[r] = ord2f(rmSrc[r]); }
}

// h = max(h, max(p0,p1) - rmA[r]); rmH=max(rmH,0); optional pool atomics.
__global__ void resid2_k(const float4* __restrict__ p0, const float4* __restrict__ p1,
                         const unsigned* __restrict__ rmA,
                         float4* __restrict__ h, float* __restrict__ rmH,
                         unsigned* __restrict__ poolAtom)
{
    int idx = blockIdx.x * 128 + threadIdx.x;     // [0, MTOT*32)
    int r = idx >> 5;
    float rm = ord2f(rmA[r]);
    float4 a = p0[idx], b = p1[idx], hv = h[idx];
    hv.x = fmaxf(hv.x, fmaxf(a.x, b.x) - rm);
    hv.y = fmaxf(hv.y, fmaxf(a.y, b.y) - rm);
    hv.z = fmaxf(hv.z, fmaxf(a.z, b.z) - rm);
    hv.w = fmaxf(hv.w, fmaxf(a.w, b.w) - rm);
    h[idx] = hv;
    if ((idx & 31) == 0) rmH[r] = fmaxf(rmH[r], 0.f);
    if (poolAtom) {
        unsigned* pa = poolAtom + (r / NPATCH) * DD + (idx & 31) * 4;
        atomicMax(pa + 0, f2ord(hv.x));
        atomicMax(pa + 1, f2ord(hv.y));
        atomicMax(pa + 2, f2ord(hv.z));
        atomicMax(pa + 3, f2ord(hv.w));
    }
}

// logits[b,c] = max_d(pooled[b,d] + W[c,d]) * ls
__global__ void head_k(const float* __restrict__ W, const float* __restrict__ ls,
                       const unsigned* __restrict__ poolAtom, float* __restrict__ out)
{
    __shared__ float p[DD];
    int b = blockIdx.y, t = threadIdx.x;
    p[t] = ord2f(poolAtom[b * DD + t]);
    __syncthreads();
    int c = blockIdx.x * 128 + t;
    if (c < NCLS) {
        float acc = NEG_INF;
        const float* w = W + (long)c * DD;
#pragma unroll 4
        for (int d = 0; d < DD; ++d) acc = fmaxf(acc, p[d] + w[d]);
        out[(long)b * NCLS + c] = acc * ls[0];
    }
}

// ---------------------------------------------------------------------------

extern "C" void kernel_launch(void* const* d_in, const int* in_sizes, int n_in,
                              void* d_out, int out_size)
{
    (void)in_sizes; (void)n_in; (void)out_size;
    const float* x       = (const float*)d_in[0];
    const float* embed_W = (const float*)d_in[1];
    const float* pos     = (const float*)d_in[2];
    const float* head_W  = (const float*)d_in[15];
    const float* lscale  = (const float*)d_in[16];
    float* out = (float*)d_out;

    float *h, *rmH, *q, *k, *vT, *s, *p, *h1;
    unsigned* at;
    cudaGetSymbolAddress((void**)&h,   g_h);
    cudaGetSymbolAddress((void**)&rmH, g_rmH);
    cudaGetSymbolAddress((void**)&q,   g_q);
    cudaGetSymbolAddress((void**)&k,   g_k);
    cudaGetSymbolAddress((void**)&vT,  g_vT);
    cudaGetSymbolAddress((void**)&s,   g_s);
    cudaGetSymbolAddress((void**)&p,   g_p);
    cudaGetSymbolAddress((void**)&h1,  g_h1);
    cudaGetSymbolAddress((void**)&at,  g_atoms);

    float* p1 = p + MTOT * DD;
    unsigned* rmE     = at;
    unsigned* poolAt  = at + 5 * MTOT;

    cudaMemsetAsync(at, 0, (5 * MTOT + BB * DD) * sizeof(unsigned));

    // embed: patchify fused, K=256 split2 -> p0/p1 ; +pos & rowmax in epilogue
    tg<M_EMBED><<<dim3(4, 49, 2), 128>>>(x, embed_W, 0, 0, p, p1, 0,
        0, rmE, pos, MTOT, DD, 256, DD, 0, 0, 0, 1, 128);
    combine2_k<<<392, 128>>>((const float4*)p, (const float4*)p1, rmE,
                             (float4*)h, rmH);

    for (int l = 0; l < 2; ++l) {
        const float* qW  = (const float*)d_in[3 + 6 * l];
        const float* kW  = (const float*)d_in[4 + 6 * l];
        const float* vW  = (const float*)d_in[5 + 6 * l];
        const float* f1W = (const float*)d_in[6 + 6 * l];
        const float* f2W = (const float*)d_in[7 + 6 * l];
        const float* tau = (const float*)d_in[8 + 6 * l];
        unsigned* rmAt = at + (1 + 2 * l) * MTOT;
        unsigned* rmFf = at + (2 + 2 * l) * MTOT;

        // q/k/v fused (N=384): A=h, epilogue subtracts rmH; vT coalesced store
        tg<M_QKV><<<dim3(12, 49, 1), 128>>>(h, qW, kW, vW, q, k, vT,
            rmH, 0, 0, MTOT, 384, DD, 0, 0, 0, 0, 0, DD);

        // scores per batch: (196x128) x (196x128)^T -> (196 x 224), pads -inf
        tg<M_SCORES><<<dim3(7, 7, 8), 128>>>(q, k, 0, 0, s, 0, 0,
            0, 0, 0, NPATCH, NPATCH, DD, NPAD,
            NPATCH * DD, NPATCH * DD, NPATCH * NPAD, 0, DD);

        // attn out per batch: K=224 split2 -> p0/p1 + atomic rowmax
        tg<M_ATT><<<dim3(4, 7, 16), 128>>>(s, vT, 0, 0, p, p1, 0,
            0, rmAt, 0, NPATCH, DD, NPAD, DD,
            NPATCH * NPAD, DD * NPAD, NPATCH * DD, 1, 128);
        resid2_k<<<392, 128>>>((const float4*)p, (const float4*)p1, rmAt,
                               (float4*)h, rmH, 0);

        // ff1: A=h, epilogue subtracts rmH then max(tau) -> h1
        tg<M_FF1><<<dim3(8, 49, 1), 128>>>(h, f1W, 0, 0, h1, 0, 0,
            rmH, 0, tau, MTOT, DFF, DD, DFF, 0, 0, 0, 0, DD);

        // ff2: K=256 split2 -> p0/p1 + atomic rowmax
        tg<M_FF2><<<dim3(4, 49, 2), 128>>>(h1, f2W, 0, 0, p, p1, 0,
            0, rmFf, 0, MTOT, DD, DFF, DD, 0, 0, 0, 1, 128);
        resid2_k<<<392, 128>>>((const float4*)p, (const float4*)p1, rmFf,
                               (float4*)h, rmH, (l == 1) ? poolAt : 0);
    }

    head_k<<<dim3(8, BB), 128>>>(head_W, lscale, poolAt, out);
}